// round 15
// baseline (speedup 1.0000x reference)
#include <cuda_runtime.h>

// ---------------------------------------------------------------------------
// TalkerAttentionV2: single-token GQA decode attention + full KV-cache copy.
// B=16, HID=1024, NH=16, NKV=8, HD=128, S=4096.
// R15 = R14 + restructured k_qkv: 1024 blocks x 256 thr, 4 rows/block,
// 4 prefetched weight loads per thread (weight stream was latency-bound at
// 714 GB/s with MLP=2). Tail normrope election now counts 32 blocks/head.
// No cache hints (regressed 2x); no occupancy caps on k_attn (register cliff).
// ---------------------------------------------------------------------------

namespace {
constexpr int B    = 16;
constexpr int HID  = 1024;
constexpr int NH   = 16;
constexpr int NKV  = 8;
constexpr int HD   = 128;
constexpr int S    = 4096;
constexpr int DKV  = NKV * HD;          // 1024
constexpr int NQ   = NH * HD;           // 2048
constexpr int QKV_ROWS = NQ + 2 * DKV;  // 4096
constexpr float EPS = 1e-6f;
constexpr float SCALE = 0.0883883476483184405f; // 128^-0.5
constexpr int SC   = 4;                 // S chunks per (b,kvh) -> 512 blocks
constexpr int SLEN = S / SC;            // 1024
constexpr int CF4  = SLEN / 4;          // 256 float4 columns per chunk
}

// Scratch (static device globals)
__device__ __align__(16) float g_qkv[B][QKV_ROWS];      // raw q|k|v projections
__device__ __align__(16) float g_q[B][NH][HD];          // normed+roped q
__device__ __align__(16) float g_kn[B][NKV][HD];        // normed+roped new k
__device__ __align__(16) float g_pout[B][NH][SC][HD];   // partial V-weighted sums
__device__ __align__(16) float2 g_ms[B][NH][SC];        // per-chunk (max, sumexp)
__device__ __align__(16) float g_attnout[B][NQ];        // combined attention out
__device__ int g_pos[B];
__device__ int g_cnt[B][NKV];                           // attn tail counters
__device__ int g_hcnt[NH + NKV];                        // qkv tail counters

// ---------------------------------------------------------------------------
// 1. QKV projection + tail-fused RMSNorm/RoPE/pos-scan.
//    Grid 1024 x 256 threads. Block handles 4 consecutive rows; 2 warps per
//    row; each thread prefetches 4 weight float4 (4 independent DRAM loads).
//    32nd-arriving block of each head runs normrope for that head.
// ---------------------------------------------------------------------------
__global__ __launch_bounds__(256) void k_qkv(const float* __restrict__ x,
                      const float* __restrict__ Wq,
                      const float* __restrict__ Wk,
                      const float* __restrict__ Wv,
                      const float* __restrict__ cosb,
                      const float* __restrict__ sinb,
                      const float* __restrict__ qw,
                      const float* __restrict__ kw,
                      const float* __restrict__ um) {
    int warp = threadIdx.x >> 5, lane = threadIdx.x & 31;
    int rl   = warp >> 1;            // row within block (0..3)
    int half = warp & 1;             // which half of HID this warp covers
    int r    = blockIdx.x * 4 + rl;

    const float* wrow;
    if (r < NQ)            wrow = Wq + (size_t)r * HID;
    else if (r < NQ + DKV) wrow = Wk + (size_t)(r - NQ) * HID;
    else                   wrow = Wv + (size_t)(r - NQ - DKV) * HID;

    const float4* w4 = (const float4*)wrow;
    const float4* x4 = (const float4*)x;
    int cbase = half * 128 + lane;   // float4 index; +j*32, j<4

    // Prefetch 4 independent weight vectors (the DRAM-latency cover).
    float4 wv[4];
#pragma unroll
    for (int j = 0; j < 4; j++) wv[j] = w4[cbase + j * 32];

    float acc[B];
#pragma unroll
    for (int b = 0; b < B; b++) acc[b] = 0.0f;

#pragma unroll
    for (int j = 0; j < 4; j++) {
        int c = cbase + j * 32;
#pragma unroll
        for (int b = 0; b < B; b++) {
            float4 xv = x4[b * (HID / 4) + c];
            acc[b] += wv[j].x * xv.x + wv[j].y * xv.y +
                      wv[j].z * xv.z + wv[j].w * xv.w;
        }
    }

    __shared__ float red[8][B];
    __shared__ int s_last;
#pragma unroll
    for (int b = 0; b < B; b++) {
        float v = acc[b];
#pragma unroll
        for (int o = 16; o; o >>= 1) v += __shfl_xor_sync(0xffffffffu, v, o);
        acc[b] = v;
    }
    if (lane == 0) {
#pragma unroll
        for (int b = 0; b < B; b++) red[warp][b] = acc[b];
    }
    __syncthreads();
    if (half == 0 && lane < B)
        g_qkv[lane][r] = red[warp][lane] + red[warp + 1][lane];

    // ---- Tail: per-head last-block (of 32) election runs RMSNorm+RoPE.
    if (blockIdx.x >= (NQ + DKV) / 4) return;   // V rows need no norm
    int head = blockIdx.x >> 5;                 // 0..15 q, 16..23 k

    __threadfence();
    __syncthreads();
    if (threadIdx.x == 0) s_last = atomicAdd(&g_hcnt[head], 1);
    __syncthreads();
    if (s_last != 31) return;
    __threadfence();                     // acquire: other blocks' g_qkv writes

    // pos scan: q-head h scans the one-hot mask for batch b=h
    if (head < NH) {
        for (int s = threadIdx.x; s < S; s += 256)
            if (um[head * S + s] > 0.5f) g_pos[head] = s;
    }

    bool isq = (head < NH);
    int rowbase = isq ? head * HD : NQ + (head - NH) * HD;
    const float* wnv = isq ? qw : kw;
    float4 wreg = *(const float4*)(wnv + lane * 4);
    float sgn = (lane < 16) ? -1.0f : 1.0f;   // rotate-half sign

    for (int bb = warp; bb < B; bb += 8) {
        float4 v = *(const float4*)&g_qkv[bb][rowbase + lane * 4];
        float sq = v.x * v.x + v.y * v.y + v.z * v.z + v.w * v.w;
#pragma unroll
        for (int o = 16; o; o >>= 1) sq += __shfl_xor_sync(0xffffffffu, sq, o);
        float rn = rsqrtf(sq * (1.0f / HD) + EPS);
        float4 n = make_float4(v.x * rn * wreg.x, v.y * rn * wreg.y,
                               v.z * rn * wreg.z, v.w * rn * wreg.w);
        float4 rot;
        rot.x = sgn * __shfl_xor_sync(0xffffffffu, n.x, 16);
        rot.y = sgn * __shfl_xor_sync(0xffffffffu, n.y, 16);
        rot.z = sgn * __shfl_xor_sync(0xffffffffu, n.z, 16);
        rot.w = sgn * __shfl_xor_sync(0xffffffffu, n.w, 16);
        float4 c  = *(const float4*)(cosb + bb * HD + lane * 4);
        float4 sn = *(const float4*)(sinb + bb * HD + lane * 4);
        float4 o4 = make_float4(n.x * c.x + rot.x * sn.x,
                                n.y * c.y + rot.y * sn.y,
                                n.z * c.z + rot.z * sn.z,
                                n.w * c.w + rot.w * sn.w);
        if (isq) *(float4*)&g_q[bb][head][lane * 4] = o4;
        else     *(float4*)&g_kn[bb][head - NH][lane * 4] = o4;
    }
    if (threadIdx.x == 0) g_hcnt[head] = 0;   // reset for next graph replay
}

// ---------------------------------------------------------------------------
// 2. Fused flash-decode chunk kernel + tail combine. Grid 512, 256 threads.
// ---------------------------------------------------------------------------
__global__ __launch_bounds__(256) void k_attn(const float* __restrict__ kcache,
                                              const float* __restrict__ vcache,
                                              const float* __restrict__ kpm,
                                              float* __restrict__ outk,
                                              float* __restrict__ outv) {
    int id    = blockIdx.x;
    int chunk = id & (SC - 1);
    int kvh   = (id >> 2) & (NKV - 1);
    int b     = id >> 5;
    int s0    = chunk * SLEN;
    int t     = threadIdx.x;   // 256

    __shared__ float q0s[HD], q1s[HD], kns[HD], vns[HD];
    __shared__ __align__(16) float e0[SLEN], e1[SLEN];
    __shared__ float sr0[8], sr1[8];
    __shared__ int s_last;

    if (t < HD) {
        q0s[t] = g_q[b][2 * kvh][t];
        q1s[t] = g_q[b][2 * kvh + 1][t];
        kns[t] = g_kn[b][kvh][t];
        vns[t] = g_qkv[b][NQ + DKV + kvh * HD + t];
    }
    __syncthreads();

    int posb = g_pos[b];
    size_t rowbase = ((size_t)(b * DKV + kvh * HD) * S + s0) >> 2; // float4 idx

    // ---- Phase 1: K copy + scores. Thread t owns float4 column t (256 cols),
    //      loops all HD=128 rows (R2 k_scores structure: proven 74% DRAM).
    {
        int c   = t;                 // 0..CF4-1
        int gs  = s0 + (c << 2);
        int rel = posb - gs;
        const float4* src = (const float4*)kcache + rowbase + c;
        float4*       dst = (float4*)outk + rowbase + c;

        float a00 = 0, a01 = 0, a02 = 0, a03 = 0;
        float a10 = 0, a11 = 0, a12 = 0, a13 = 0;
#pragma unroll 4
        for (int d = 0; d < HD; d++) {
            float4 v = src[(size_t)d * (S / 4)];
            if ((unsigned)rel < 4u) (&v.x)[rel] = kns[d];
            dst[(size_t)d * (S / 4)] = v;
            float q0 = q0s[d], q1 = q1s[d];
            a00 += q0 * v.x; a01 += q0 * v.y; a02 += q0 * v.z; a03 += q0 * v.w;
            a10 += q1 * v.x; a11 += q1 * v.y; a12 += q1 * v.z; a13 += q1 * v.w;
        }

        float4 m = *(const float4*)(kpm + (size_t)b * S + gs);
        *(float4*)&e0[c << 2] = make_float4(
            a00 * SCALE + m.x, a01 * SCALE + m.y,
            a02 * SCALE + m.z, a03 * SCALE + m.w);
        *(float4*)&e1[c << 2] = make_float4(
            a10 * SCALE + m.x, a11 * SCALE + m.y,
            a12 * SCALE + m.z, a13 * SCALE + m.w);
        __syncthreads();
    }

    // ---- Phase 2: local softmax over the chunk (two heads)
    {
        float m0 = -1e30f, m1 = -1e30f;
        for (int s = t; s < SLEN; s += 256) {
            m0 = fmaxf(m0, e0[s]);
            m1 = fmaxf(m1, e1[s]);
        }
#pragma unroll
        for (int o = 16; o; o >>= 1) {
            m0 = fmaxf(m0, __shfl_xor_sync(0xffffffffu, m0, o));
            m1 = fmaxf(m1, __shfl_xor_sync(0xffffffffu, m1, o));
        }
        if ((t & 31) == 0) { sr0[t >> 5] = m0; sr1[t >> 5] = m1; }
        __syncthreads();
        m0 = sr0[0]; m1 = sr1[0];
#pragma unroll
        for (int w = 1; w < 8; w++) {
            m0 = fmaxf(m0, sr0[w]);
            m1 = fmaxf(m1, sr1[w]);
        }
        __syncthreads();

        float s0a = 0.0f, s1a = 0.0f;
        for (int s = t; s < SLEN; s += 256) {
            float x0 = __expf(e0[s] - m0); e0[s] = x0; s0a += x0;
            float x1 = __expf(e1[s] - m1); e1[s] = x1; s1a += x1;
        }
#pragma unroll
        for (int o = 16; o; o >>= 1) {
            s0a += __shfl_xor_sync(0xffffffffu, s0a, o);
            s1a += __shfl_xor_sync(0xffffffffu, s1a, o);
        }
        if ((t & 31) == 0) { sr0[t >> 5] = s0a; sr1[t >> 5] = s1a; }
        __syncthreads();
        if (t == 0) {
            float t0 = 0, t1 = 0;
#pragma unroll
            for (int w = 0; w < 8; w++) { t0 += sr0[w]; t1 += sr1[w]; }
            g_ms[b][2 * kvh][chunk]     = make_float2(m0, t0);
            g_ms[b][2 * kvh + 1][chunk] = make_float2(m1, t1);
        }
        __syncthreads();
    }

    // ---- Phase 3: V copy + partial weighted sums. Warp w owns d rows w,w+8,..
    //      e0/e1 read as float4 (LDS.128, conflict-free). 8 loads in flight/d.
    {
        int warp = t >> 5, lane = t & 31;
        const float4* src = (const float4*)vcache + rowbase;
        float4*       dst = (float4*)outv + rowbase;

        for (int d = warp; d < HD; d += 8) {
            float p0 = 0.0f, p1 = 0.0f;
            size_t rb = (size_t)d * (S / 4);
#pragma unroll
            for (int it = 0; it < CF4 / 32; it++) {
                int si = it * 32 + lane;
                float4 v = src[rb + si];
                int sl = si << 2;
                int rel = posb - (s0 + sl);
                if ((unsigned)rel < 4u) (&v.x)[rel] = vns[d];
                dst[rb + si] = v;
                float4 w0 = *(const float4*)&e0[sl];
                float4 w1 = *(const float4*)&e1[sl];
                p0 += w0.x * v.x + w0.y * v.y + w0.z * v.z + w0.w * v.w;
                p1 += w1.x * v.x + w1.y * v.y + w1.z * v.z + w1.w * v.w;
            }
#pragma unroll
            for (int o = 16; o; o >>= 1) {
                p0 += __shfl_xor_sync(0xffffffffu, p0, o);
                p1 += __shfl_xor_sync(0xffffffffu, p1, o);
            }
            if (lane == 0) {
                g_pout[b][2 * kvh][chunk][d]     = p0;
                g_pout[b][2 * kvh + 1][chunk][d] = p1;
            }
        }
    }

    // ---- Tail: last chunk block for this (b,kvh) combines all SC chunks.
    __threadfence();
    __syncthreads();
    if (t == 0) s_last = atomicAdd(&g_cnt[b][kvh], 1);
    __syncthreads();
    if (s_last == SC - 1) {
        __threadfence();                 // acquire side: other blocks' writes
        int h = 2 * kvh + (t >> 7);      // threads 0..127 -> head0, 128..255 -> head1
        int d = t & (HD - 1);

        float2 ms[SC];
        float po[SC];
        float M = -1e30f;
#pragma unroll
        for (int c = 0; c < SC; c++) {
            ms[c] = g_ms[b][h][c];
            po[c] = g_pout[b][h][c][d];
            M = fmaxf(M, ms[c].x);
        }
        float tot = 0.0f, acc = 0.0f;
#pragma unroll
        for (int c = 0; c < SC; c++) {
            float w = __expf(ms[c].x - M);
            tot += w * ms[c].y;
            acc += w * po[c];
        }
        g_attnout[b][h * HD + d] = acc / tot;
        if (t == 0) g_cnt[b][kvh] = 0;   // reset for next graph replay
    }
}

// ---------------------------------------------------------------------------
// 3. Output projection: 512 blocks x 256 threads; block handles j-rows
//    (j, j+512). Direct loads; attnout stays L1/L2-resident.
// ---------------------------------------------------------------------------
__global__ __launch_bounds__(256) void k_oproj(const float* __restrict__ Wo,
                                               float* __restrict__ out) {
    int j0 = blockIdx.x;
    int j1 = blockIdx.x + 512;
    const float4* wa = (const float4*)(Wo + (size_t)j0 * NQ);
    const float4* wb = (const float4*)(Wo + (size_t)j1 * NQ);

    float acc0[B], acc1[B];
#pragma unroll
    for (int b = 0; b < B; b++) { acc0[b] = 0.0f; acc1[b] = 0.0f; }

#pragma unroll
    for (int i = 0; i < 2; i++) {
        int r = threadIdx.x + i * 256;     // 512 float4 per row
        float4 w0 = wa[r];
        float4 w1 = wb[r];
#pragma unroll
        for (int b = 0; b < B; b++) {
            float4 a = *(const float4*)&g_attnout[b][r << 2];
            acc0[b] += w0.x * a.x + w0.y * a.y + w0.z * a.z + w0.w * a.w;
            acc1[b] += w1.x * a.x + w1.y * a.y + w1.z * a.z + w1.w * a.w;
        }
    }

    __shared__ float red[8][B];
    int lane = threadIdx.x & 31, warp = threadIdx.x >> 5;

    // reduce + write j0
#pragma unroll
    for (int b = 0; b < B; b++) {
        float v = acc0[b];
#pragma unroll
        for (int o = 16; o; o >>= 1) v += __shfl_xor_sync(0xffffffffu, v, o);
        if (lane == 0) red[warp][b] = v;
    }
    __syncthreads();
    if (threadIdx.x < B) {
        float v = 0.0f;
#pragma unroll
        for (int w = 0; w < 8; w++) v += red[w][threadIdx.x];
        out[threadIdx.x * HID + j0] = v;
    }
    __syncthreads();

    // reduce + write j1
#pragma unroll
    for (int b = 0; b < B; b++) {
        float v = acc1[b];
#pragma unroll
        for (int o = 16; o; o >>= 1) v += __shfl_xor_sync(0xffffffffu, v, o);
        if (lane == 0) red[warp][b] = v;
    }
    __syncthreads();
    if (threadIdx.x < B) {
        float v = 0.0f;
#pragma unroll
        for (int w = 0; w < 8; w++) v += red[w][threadIdx.x];
        out[threadIdx.x * HID + j1] = v;
    }
}

// ---------------------------------------------------------------------------
// Launch
// ---------------------------------------------------------------------------
extern "C" void kernel_launch(void* const* d_in, const int* in_sizes, int n_in,
                              void* d_out, int out_size) {
    (void)in_sizes; (void)n_in; (void)out_size;
    const float* x   = (const float*)d_in[0];
    const float* rc  = (const float*)d_in[1];
    const float* rs  = (const float*)d_in[2];
    const float* kpm = (const float*)d_in[3];
    const float* um  = (const float*)d_in[4];
    const float* kc  = (const float*)d_in[5];
    const float* vc  = (const float*)d_in[6];
    const float* Wq  = (const float*)d_in[7];
    const float* Wk  = (const float*)d_in[8];
    const float* Wv  = (const float*)d_in[9];
    const float* Wo  = (const float*)d_in[10];
    const float* qw  = (const float*)d_in[11];
    const float* kw  = (const float*)d_in[12];

    float* out  = (float*)d_out;
    float* outk = out + (size_t)B * HID;
    float* outv = outk + (size_t)B * DKV * S;

    k_qkv<<<QKV_ROWS / 4, 256>>>(x, Wq, Wk, Wv, rc, rs, qw, kw, um);
    k_attn<<<B * NKV * SC, 256>>>(kc, vc, kpm, outk, outv);
    k_oproj<<<512, 256>>>(Wo, out);
}

// round 16
// speedup vs baseline: 1.0189x; 1.0189x over previous
#include <cuda_runtime.h>

// ---------------------------------------------------------------------------
// TalkerAttentionV2: single-token GQA decode attention + full KV-cache copy.
// B=16, HID=1024, NH=16, NKV=8, HD=128, S=4096.
// R16 = R14 (best known chain) with k_qkv doing 2 consecutive rows per block:
// same 32 x L1-loads per thread now feed two rows (x-reuse), weight MLP 2->4.
// No cache hints (regressed 2x); no occupancy caps on k_attn (register cliff).
// ---------------------------------------------------------------------------

namespace {
constexpr int B    = 16;
constexpr int HID  = 1024;
constexpr int NH   = 16;
constexpr int NKV  = 8;
constexpr int HD   = 128;
constexpr int S    = 4096;
constexpr int DKV  = NKV * HD;          // 1024
constexpr int NQ   = NH * HD;           // 2048
constexpr int QKV_ROWS = NQ + 2 * DKV;  // 4096
constexpr float EPS = 1e-6f;
constexpr float SCALE = 0.0883883476483184405f; // 128^-0.5
constexpr int SC   = 4;                 // S chunks per (b,kvh) -> 512 blocks
constexpr int SLEN = S / SC;            // 1024
constexpr int CF4  = SLEN / 4;          // 256 float4 columns per chunk
}

// Scratch (static device globals)
__device__ __align__(16) float g_qkv[B][QKV_ROWS];      // raw q|k|v projections
__device__ __align__(16) float g_q[B][NH][HD];          // normed+roped q
__device__ __align__(16) float g_kn[B][NKV][HD];        // normed+roped new k
__device__ __align__(16) float g_pout[B][NH][SC][HD];   // partial V-weighted sums
__device__ __align__(16) float2 g_ms[B][NH][SC];        // per-chunk (max, sumexp)
__device__ __align__(16) float g_attnout[B][NQ];        // combined attention out
__device__ int g_pos[B];
__device__ int g_cnt[B][NKV];                           // attn tail counters
__device__ int g_hcnt[NH + NKV];                        // qkv tail counters

// ---------------------------------------------------------------------------
// 1. QKV projection + tail-fused RMSNorm/RoPE/pos-scan.
//    Grid 2048 x 128 threads; block handles rows (2*bid, 2*bid+1). Each
//    thread: 2 k-chunks x 2 rows = 4 independent weight loads; the 32 x
//    L1-loads are shared between both rows (halves L1 pressure per row).
//    64th-arriving block of each head runs normrope for that head.
// ---------------------------------------------------------------------------
__global__ __launch_bounds__(128) void k_qkv(const float* __restrict__ x,
                      const float* __restrict__ Wq,
                      const float* __restrict__ Wk,
                      const float* __restrict__ Wv,
                      const float* __restrict__ cosb,
                      const float* __restrict__ sinb,
                      const float* __restrict__ qw,
                      const float* __restrict__ kw,
                      const float* __restrict__ um) {
    int r0 = blockIdx.x * 2;
    int r1 = r0 + 1;

    auto rowptr = [&](int r) -> const float* {
        if (r < NQ)            return Wq + (size_t)r * HID;
        else if (r < NQ + DKV) return Wk + (size_t)(r - NQ) * HID;
        else                   return Wv + (size_t)(r - NQ - DKV) * HID;
    };
    const float4* wr0 = (const float4*)rowptr(r0);
    const float4* wr1 = (const float4*)rowptr(r1);
    const float4* x4  = (const float4*)x;

    int c0 = threadIdx.x;         // k-chunk 0
    int c1 = threadIdx.x + 128;   // k-chunk 1

    // 4 independent DRAM weight loads (MLP=4).
    float4 w00 = wr0[c0];
    float4 w01 = wr0[c1];
    float4 w10 = wr1[c0];
    float4 w11 = wr1[c1];

    float acc0[B], acc1[B];
#pragma unroll
    for (int b = 0; b < B; b++) { acc0[b] = 0.0f; acc1[b] = 0.0f; }

#pragma unroll
    for (int b = 0; b < B; b++) {
        float4 xa = x4[b * (HID / 4) + c0];
        float4 xb = x4[b * (HID / 4) + c1];
        acc0[b] += w00.x * xa.x + w00.y * xa.y + w00.z * xa.z + w00.w * xa.w
                 + w01.x * xb.x + w01.y * xb.y + w01.z * xb.z + w01.w * xb.w;
        acc1[b] += w10.x * xa.x + w10.y * xa.y + w10.z * xa.z + w10.w * xa.w
                 + w11.x * xb.x + w11.y * xb.y + w11.z * xb.z + w11.w * xb.w;
    }

    __shared__ float red[4][B];
    __shared__ int s_last;
    int lane = threadIdx.x & 31, warp = threadIdx.x >> 5;

    // reduce + store row r0
#pragma unroll
    for (int b = 0; b < B; b++) {
        float v = acc0[b];
#pragma unroll
        for (int o = 16; o; o >>= 1) v += __shfl_xor_sync(0xffffffffu, v, o);
        if (lane == 0) red[warp][b] = v;
    }
    __syncthreads();
    if (threadIdx.x < B)
        g_qkv[threadIdx.x][r0] = red[0][threadIdx.x] + red[1][threadIdx.x] +
                                 red[2][threadIdx.x] + red[3][threadIdx.x];
    __syncthreads();

    // reduce + store row r1
#pragma unroll
    for (int b = 0; b < B; b++) {
        float v = acc1[b];
#pragma unroll
        for (int o = 16; o; o >>= 1) v += __shfl_xor_sync(0xffffffffu, v, o);
        if (lane == 0) red[warp][b] = v;
    }
    __syncthreads();
    if (threadIdx.x < B)
        g_qkv[threadIdx.x][r1] = red[0][threadIdx.x] + red[1][threadIdx.x] +
                                 red[2][threadIdx.x] + red[3][threadIdx.x];

    // ---- Tail: per-head last-block (of 64) election runs RMSNorm+RoPE.
    if (blockIdx.x >= (NQ + DKV) / 2) return;   // V rows need no norm
    int head = blockIdx.x >> 6;                 // 0..15 q, 16..23 k

    __threadfence();
    __syncthreads();
    if (threadIdx.x == 0) s_last = atomicAdd(&g_hcnt[head], 1);
    __syncthreads();
    if (s_last != 63) return;
    __threadfence();                     // acquire: other blocks' g_qkv writes

    // pos scan: q-head h scans the one-hot mask for batch b=h
    if (head < NH) {
        for (int s = threadIdx.x; s < S; s += 128)
            if (um[head * S + s] > 0.5f) g_pos[head] = s;
    }

    bool isq = (head < NH);
    int rowbase = isq ? head * HD : NQ + (head - NH) * HD;
    const float* wnv = isq ? qw : kw;
    float4 wreg = *(const float4*)(wnv + lane * 4);
    float sgn = (lane < 16) ? -1.0f : 1.0f;   // rotate-half sign

    for (int bb = warp; bb < B; bb += 4) {
        float4 v = *(const float4*)&g_qkv[bb][rowbase + lane * 4];
        float sq = v.x * v.x + v.y * v.y + v.z * v.z + v.w * v.w;
#pragma unroll
        for (int o = 16; o; o >>= 1) sq += __shfl_xor_sync(0xffffffffu, sq, o);
        float rn = rsqrtf(sq * (1.0f / HD) + EPS);
        float4 n = make_float4(v.x * rn * wreg.x, v.y * rn * wreg.y,
                               v.z * rn * wreg.z, v.w * rn * wreg.w);
        float4 rot;
        rot.x = sgn * __shfl_xor_sync(0xffffffffu, n.x, 16);
        rot.y = sgn * __shfl_xor_sync(0xffffffffu, n.y, 16);
        rot.z = sgn * __shfl_xor_sync(0xffffffffu, n.z, 16);
        rot.w = sgn * __shfl_xor_sync(0xffffffffu, n.w, 16);
        float4 c  = *(const float4*)(cosb + bb * HD + lane * 4);
        float4 sn = *(const float4*)(sinb + bb * HD + lane * 4);
        float4 o4 = make_float4(n.x * c.x + rot.x * sn.x,
                                n.y * c.y + rot.y * sn.y,
                                n.z * c.z + rot.z * sn.z,
                                n.w * c.w + rot.w * sn.w);
        if (isq) *(float4*)&g_q[bb][head][lane * 4] = o4;
        else     *(float4*)&g_kn[bb][head - NH][lane * 4] = o4;
    }
    if (threadIdx.x == 0) g_hcnt[head] = 0;   // reset for next graph replay
}

// ---------------------------------------------------------------------------
// 2. Fused flash-decode chunk kernel + tail combine. Grid 512, 256 threads.
// ---------------------------------------------------------------------------
__global__ __launch_bounds__(256) void k_attn(const float* __restrict__ kcache,
                                              const float* __restrict__ vcache,
                                              const float* __restrict__ kpm,
                                              float* __restrict__ outk,
                                              float* __restrict__ outv) {
    int id    = blockIdx.x;
    int chunk = id & (SC - 1);
    int kvh   = (id >> 2) & (NKV - 1);
    int b     = id >> 5;
    int s0    = chunk * SLEN;
    int t     = threadIdx.x;   // 256

    __shared__ float q0s[HD], q1s[HD], kns[HD], vns[HD];
    __shared__ __align__(16) float e0[SLEN], e1[SLEN];
    __shared__ float sr0[8], sr1[8];
    __shared__ int s_last;

    if (t < HD) {
        q0s[t] = g_q[b][2 * kvh][t];
        q1s[t] = g_q[b][2 * kvh + 1][t];
        kns[t] = g_kn[b][kvh][t];
        vns[t] = g_qkv[b][NQ + DKV + kvh * HD + t];
    }
    __syncthreads();

    int posb = g_pos[b];
    size_t rowbase = ((size_t)(b * DKV + kvh * HD) * S + s0) >> 2; // float4 idx

    // ---- Phase 1: K copy + scores. Thread t owns float4 column t (256 cols),
    //      loops all HD=128 rows (R2 k_scores structure: proven 74% DRAM).
    {
        int c   = t;                 // 0..CF4-1
        int gs  = s0 + (c << 2);
        int rel = posb - gs;
        const float4* src = (const float4*)kcache + rowbase + c;
        float4*       dst = (float4*)outk + rowbase + c;

        float a00 = 0, a01 = 0, a02 = 0, a03 = 0;
        float a10 = 0, a11 = 0, a12 = 0, a13 = 0;
#pragma unroll 4
        for (int d = 0; d < HD; d++) {
            float4 v = src[(size_t)d * (S / 4)];
            if ((unsigned)rel < 4u) (&v.x)[rel] = kns[d];
            dst[(size_t)d * (S / 4)] = v;
            float q0 = q0s[d], q1 = q1s[d];
            a00 += q0 * v.x; a01 += q0 * v.y; a02 += q0 * v.z; a03 += q0 * v.w;
            a10 += q1 * v.x; a11 += q1 * v.y; a12 += q1 * v.z; a13 += q1 * v.w;
        }

        float4 m = *(const float4*)(kpm + (size_t)b * S + gs);
        *(float4*)&e0[c << 2] = make_float4(
            a00 * SCALE + m.x, a01 * SCALE + m.y,
            a02 * SCALE + m.z, a03 * SCALE + m.w);
        *(float4*)&e1[c << 2] = make_float4(
            a10 * SCALE + m.x, a11 * SCALE + m.y,
            a12 * SCALE + m.z, a13 * SCALE + m.w);
        __syncthreads();
    }

    // ---- Phase 2: local softmax over the chunk (two heads)
    {
        float m0 = -1e30f, m1 = -1e30f;
        for (int s = t; s < SLEN; s += 256) {
            m0 = fmaxf(m0, e0[s]);
            m1 = fmaxf(m1, e1[s]);
        }
#pragma unroll
        for (int o = 16; o; o >>= 1) {
            m0 = fmaxf(m0, __shfl_xor_sync(0xffffffffu, m0, o));
            m1 = fmaxf(m1, __shfl_xor_sync(0xffffffffu, m1, o));
        }
        if ((t & 31) == 0) { sr0[t >> 5] = m0; sr1[t >> 5] = m1; }
        __syncthreads();
        m0 = sr0[0]; m1 = sr1[0];
#pragma unroll
        for (int w = 1; w < 8; w++) {
            m0 = fmaxf(m0, sr0[w]);
            m1 = fmaxf(m1, sr1[w]);
        }
        __syncthreads();

        float s0a = 0.0f, s1a = 0.0f;
        for (int s = t; s < SLEN; s += 256) {
            float x0 = __expf(e0[s] - m0); e0[s] = x0; s0a += x0;
            float x1 = __expf(e1[s] - m1); e1[s] = x1; s1a += x1;
        }
#pragma unroll
        for (int o = 16; o; o >>= 1) {
            s0a += __shfl_xor_sync(0xffffffffu, s0a, o);
            s1a += __shfl_xor_sync(0xffffffffu, s1a, o);
        }
        if ((t & 31) == 0) { sr0[t >> 5] = s0a; sr1[t >> 5] = s1a; }
        __syncthreads();
        if (t == 0) {
            float t0 = 0, t1 = 0;
#pragma unroll
            for (int w = 0; w < 8; w++) { t0 += sr0[w]; t1 += sr1[w]; }
            g_ms[b][2 * kvh][chunk]     = make_float2(m0, t0);
            g_ms[b][2 * kvh + 1][chunk] = make_float2(m1, t1);
        }
        __syncthreads();
    }

    // ---- Phase 3: V copy + partial weighted sums. Warp w owns d rows w,w+8,..
    //      e0/e1 read as float4 (LDS.128, conflict-free). 8 loads in flight/d.
    {
        int warp = t >> 5, lane = t & 31;
        const float4* src = (const float4*)vcache + rowbase;
        float4*       dst = (float4*)outv + rowbase;

        for (int d = warp; d < HD; d += 8) {
            float p0 = 0.0f, p1 = 0.0f;
            size_t rb = (size_t)d * (S / 4);
#pragma unroll
            for (int it = 0; it < CF4 / 32; it++) {
                int si = it * 32 + lane;
                float4 v = src[rb + si];
                int sl = si << 2;
                int rel = posb - (s0 + sl);
                if ((unsigned)rel < 4u) (&v.x)[rel] = vns[d];
                dst[rb + si] = v;
                float4 w0 = *(const float4*)&e0[sl];
                float4 w1 = *(const float4*)&e1[sl];
                p0 += w0.x * v.x + w0.y * v.y + w0.z * v.z + w0.w * v.w;
                p1 += w1.x * v.x + w1.y * v.y + w1.z * v.z + w1.w * v.w;
            }
#pragma unroll
            for (int o = 16; o; o >>= 1) {
                p0 += __shfl_xor_sync(0xffffffffu, p0, o);
                p1 += __shfl_xor_sync(0xffffffffu, p1, o);
            }
            if (lane == 0) {
                g_pout[b][2 * kvh][chunk][d]     = p0;
                g_pout[b][2 * kvh + 1][chunk][d] = p1;
            }
        }
    }

    // ---- Tail: last chunk block for this (b,kvh) combines all SC chunks.
    __threadfence();
    __syncthreads();
    if (t == 0) s_last = atomicAdd(&g_cnt[b][kvh], 1);
    __syncthreads();
    if (s_last == SC - 1) {
        __threadfence();                 // acquire side: other blocks' writes
        int h = 2 * kvh + (t >> 7);      // threads 0..127 -> head0, 128..255 -> head1
        int d = t & (HD - 1);

        float2 ms[SC];
        float po[SC];
        float M = -1e30f;
#pragma unroll
        for (int c = 0; c < SC; c++) {
            ms[c] = g_ms[b][h][c];
            po[c] = g_pout[b][h][c][d];
            M = fmaxf(M, ms[c].x);
        }
        float tot = 0.0f, acc = 0.0f;
#pragma unroll
        for (int c = 0; c < SC; c++) {
            float w = __expf(ms[c].x - M);
            tot += w * ms[c].y;
            acc += w * po[c];
        }
        g_attnout[b][h * HD + d] = acc / tot;
        if (t == 0) g_cnt[b][kvh] = 0;   // reset for next graph replay
    }
}

// ---------------------------------------------------------------------------
// 3. Output projection: 512 blocks x 256 threads; block handles j-rows
//    (j, j+512). Direct loads; attnout stays L1/L2-resident.
// ---------------------------------------------------------------------------
__global__ __launch_bounds__(256) void k_oproj(const float* __restrict__ Wo,
                                               float* __restrict__ out) {
    int j0 = blockIdx.x;
    int j1 = blockIdx.x + 512;
    const float4* wa = (const float4*)(Wo + (size_t)j0 * NQ);
    const float4* wb = (const float4*)(Wo + (size_t)j1 * NQ);

    float acc0[B], acc1[B];
#pragma unroll
    for (int b = 0; b < B; b++) { acc0[b] = 0.0f; acc1[b] = 0.0f; }

#pragma unroll
    for (int i = 0; i < 2; i++) {
        int r = threadIdx.x + i * 256;     // 512 float4 per row
        float4 w0 = wa[r];
        float4 w1 = wb[r];
#pragma unroll
        for (int b = 0; b < B; b++) {
            float4 a = *(const float4*)&g_attnout[b][r << 2];
            acc0[b] += w0.x * a.x + w0.y * a.y + w0.z * a.z + w0.w * a.w;
            acc1[b] += w1.x * a.x + w1.y * a.y + w1.z * a.z + w1.w * a.w;
        }
    }

    __shared__ float red[8][B];
    int lane = threadIdx.x & 31, warp = threadIdx.x >> 5;

    // reduce + write j0
#pragma unroll
    for (int b = 0; b < B; b++) {
        float v = acc0[b];
#pragma unroll
        for (int o = 16; o; o >>= 1) v += __shfl_xor_sync(0xffffffffu, v, o);
        if (lane == 0) red[warp][b] = v;
    }
    __syncthreads();
    if (threadIdx.x < B) {
        float v = 0.0f;
#pragma unroll
        for (int w = 0; w < 8; w++) v += red[w][threadIdx.x];
        out[threadIdx.x * HID + j0] = v;
    }
    __syncthreads();

    // reduce + write j1
#pragma unroll
    for (int b = 0; b < B; b++) {
        float v = acc1[b];
#pragma unroll
        for (int o = 16; o; o >>= 1) v += __shfl_xor_sync(0xffffffffu, v, o);
        if (lane == 0) red[warp][b] = v;
    }
    __syncthreads();
    if (threadIdx.x < B) {
        float v = 0.0f;
#pragma unroll
        for (int w = 0; w < 8; w++) v += red[w][threadIdx.x];
        out[threadIdx.x * HID + j1] = v;
    }
}

// ---------------------------------------------------------------------------
// Launch
// ---------------------------------------------------------------------------
extern "C" void kernel_launch(void* const* d_in, const int* in_sizes, int n_in,
                              void* d_out, int out_size) {
    (void)in_sizes; (void)n_in; (void)out_size;
    const float* x   = (const float*)d_in[0];
    const float* rc  = (const float*)d_in[1];
    const float* rs  = (const float*)d_in[2];
    const float* kpm = (const float*)d_in[3];
    const float* um  = (const float*)d_in[4];
    const float* kc  = (const float*)d_in[5];
    const float* vc  = (const float*)d_in[6];
    const float* Wq  = (const float*)d_in[7];
    const float* Wk  = (const float*)d_in[8];
    const float* Wv  = (const float*)d_in[9];
    const float* Wo  = (const float*)d_in[10];
    const float* qw  = (const float*)d_in[11];
    const float* kw  = (const float*)d_in[12];

    float* out  = (float*)d_out;
    float* outk = out + (size_t)B * HID;
    float* outv = outk + (size_t)B * DKV * S;

    k_qkv<<<QKV_ROWS / 2, 128>>>(x, Wq, Wk, Wv, rc, rs, qw, kw, um);
    k_attn<<<B * NKV * SC, 256>>>(kc, vc, kpm, outk, outv);
    k_oproj<<<512, 256>>>(Wo, out);
}

// round 17
// speedup vs baseline: 1.0856x; 1.0654x over previous
#include <cuda_runtime.h>

// ---------------------------------------------------------------------------
// TalkerAttentionV2: single-token GQA decode attention + full KV-cache copy.
// B=16, HID=1024, NH=16, NKV=8, HD=128, S=4096.
// R17 = R14 chain (best, 207.1us) with k_qkv rewritten as a tiled GEMM:
// 256 blocks x 256 thr, 16 rows/block, x staged in smem (swizzled, 2 halves),
// 2 rows per thread (x-reuse), 8-deep weight-load MLP. Prior qkv attempts
// failed because x was re-read through L1 per row; this removes that.
// No cache hints (regressed 2x); no occupancy caps on k_attn (register cliff).
// ---------------------------------------------------------------------------

namespace {
constexpr int B    = 16;
constexpr int HID  = 1024;
constexpr int NH   = 16;
constexpr int NKV  = 8;
constexpr int HD   = 128;
constexpr int S    = 4096;
constexpr int DKV  = NKV * HD;          // 1024
constexpr int NQ   = NH * HD;           // 2048
constexpr int QKV_ROWS = NQ + 2 * DKV;  // 4096
constexpr float EPS = 1e-6f;
constexpr float SCALE = 0.0883883476483184405f; // 128^-0.5
constexpr int SC   = 4;                 // S chunks per (b,kvh) -> 512 blocks
constexpr int SLEN = S / SC;            // 1024
constexpr int CF4  = SLEN / 4;          // 256 float4 columns per chunk
}

// Scratch (static device globals)
__device__ __align__(16) float g_qkv[B][QKV_ROWS];      // raw q|k|v projections
__device__ __align__(16) float g_q[B][NH][HD];          // normed+roped q
__device__ __align__(16) float g_kn[B][NKV][HD];        // normed+roped new k
__device__ __align__(16) float g_pout[B][NH][SC][HD];   // partial V-weighted sums
__device__ __align__(16) float2 g_ms[B][NH][SC];        // per-chunk (max, sumexp)
__device__ __align__(16) float g_attnout[B][NQ];        // combined attention out
__device__ int g_pos[B];
__device__ int g_cnt[B][NKV];                           // attn tail counters
__device__ int g_hcnt[NH + NKV];                        // qkv tail counters

// ---------------------------------------------------------------------------
// 1. QKV projection (tiled GEMM) + tail-fused RMSNorm/RoPE/pos-scan.
//    Grid 256 x 256 threads; block owns 16 rows. x staged in smem in two
//    512-float halves (32 KB), bank-swizzled. Thread = (row-pair rg, slice
//    ks): per half 4 float4 of each of 2 rows -> 8 independent weight loads;
//    each x LDS feeds both rows. 8th-arriving block per head runs normrope.
// ---------------------------------------------------------------------------
__global__ __launch_bounds__(256) void k_qkv(const float* __restrict__ x,
                      const float* __restrict__ Wq,
                      const float* __restrict__ Wk,
                      const float* __restrict__ Wv,
                      const float* __restrict__ cosb,
                      const float* __restrict__ sinb,
                      const float* __restrict__ qw,
                      const float* __restrict__ kw,
                      const float* __restrict__ um) {
    __shared__ __align__(16) float4 sx[B][128];   // one k-half of x: 32 KB
    __shared__ float red[8][16][B];               // warp partials: 8 KB
    __shared__ int s_last;

    int t   = threadIdx.x;
    int rg  = t & 7;          // row-group (2 rows each)
    int ksh = t >> 3;         // k-slice 0..31 (4 float4 per half)
    int lane = t & 31, warp = t >> 5;

    int r0g = blockIdx.x * 16;
    const float* wbase;
    if (r0g < NQ)            wbase = Wq + (size_t)r0g * HID;
    else if (r0g < NQ + DKV) wbase = Wk + (size_t)(r0g - NQ) * HID;
    else                     wbase = Wv + (size_t)(r0g - NQ - DKV) * HID;

    const float4* x4 = (const float4*)x;

    float acc0[B], acc1[B];
#pragma unroll
    for (int b = 0; b < B; b++) { acc0[b] = 0.0f; acc1[b] = 0.0f; }

#pragma unroll
    for (int h = 0; h < 2; h++) {
        // ---- stage x half h (16 batches x 128 float4), swizzled
        if (h) __syncthreads();          // previous half consumed
#pragma unroll
        for (int i = 0; i < 8; i++) {
            int idx = t + i * 256;       // 0..2047
            int b   = idx >> 7;
            int e   = idx & 127;
            int pe  = (e & ~3) | ((e + (e >> 2)) & 3);
            sx[b][pe] = x4[b * 256 + h * 128 + e];
        }
        __syncthreads();

        // ---- compute: 2 rows x 4 float4 weight chunks against staged x
        const float4* wa4 = (const float4*)(wbase + (size_t)(2 * rg) * HID)
                            + h * 128 + ksh * 4;
        const float4* wb4 = (const float4*)(wbase + (size_t)(2 * rg + 1) * HID)
                            + h * 128 + ksh * 4;
        float4 wva[4], wvb[4];
#pragma unroll
        for (int j = 0; j < 4; j++) { wva[j] = wa4[j]; wvb[j] = wb4[j]; }

#pragma unroll
        for (int j = 0; j < 4; j++) {
            int pe = ksh * 4 + ((j + ksh) & 3);
#pragma unroll
            for (int b = 0; b < B; b++) {
                float4 xv = sx[b][pe];
                acc0[b] += wva[j].x * xv.x + wva[j].y * xv.y +
                           wva[j].z * xv.z + wva[j].w * xv.w;
                acc1[b] += wvb[j].x * xv.x + wvb[j].y * xv.y +
                           wvb[j].z * xv.z + wvb[j].w * xv.w;
            }
        }
    }

    // ---- reduce over the 4 ks-slices within each warp (lanes rg, rg+8, ...)
#pragma unroll
    for (int b = 0; b < B; b++) {
#pragma unroll
        for (int o = 8; o <= 16; o <<= 1) {
            acc0[b] += __shfl_xor_sync(0xffffffffu, acc0[b], o);
            acc1[b] += __shfl_xor_sync(0xffffffffu, acc1[b], o);
        }
    }
    if (lane < 8) {
#pragma unroll
        for (int b = 0; b < B; b++) {
            red[warp][2 * lane][b]     = acc0[b];
            red[warp][2 * lane + 1][b] = acc1[b];
        }
    }
    __syncthreads();

    // ---- final: 16 rows x 16 batches, sum 8 warp partials
    {
        int row = t >> 4, b = t & 15;
        float v = 0.0f;
#pragma unroll
        for (int w = 0; w < 8; w++) v += red[w][row][b];
        g_qkv[b][r0g + row] = v;
    }

    // ---- Tail: per-head last-block (of 8) election runs RMSNorm+RoPE.
    if (blockIdx.x >= (NQ + DKV) / 16) return;   // V rows need no norm
    int head = blockIdx.x >> 3;                  // 0..15 q, 16..23 k

    __threadfence();
    __syncthreads();
    if (t == 0) s_last = atomicAdd(&g_hcnt[head], 1);
    __syncthreads();
    if (s_last != 7) return;
    __threadfence();                     // acquire: other blocks' g_qkv writes

    // pos scan: q-head h scans the one-hot mask for batch b=h
    if (head < NH) {
        for (int s = t; s < S; s += 256)
            if (um[head * S + s] > 0.5f) g_pos[head] = s;
    }

    bool isq = (head < NH);
    int rowbase = isq ? head * HD : NQ + (head - NH) * HD;
    const float* wnv = isq ? qw : kw;
    float4 wreg = *(const float4*)(wnv + lane * 4);
    float sgn = (lane < 16) ? -1.0f : 1.0f;   // rotate-half sign

    for (int bb = warp; bb < B; bb += 8) {
        float4 v = *(const float4*)&g_qkv[bb][rowbase + lane * 4];
        float sq = v.x * v.x + v.y * v.y + v.z * v.z + v.w * v.w;
#pragma unroll
        for (int o = 16; o; o >>= 1) sq += __shfl_xor_sync(0xffffffffu, sq, o);
        float rn = rsqrtf(sq * (1.0f / HD) + EPS);
        float4 n = make_float4(v.x * rn * wreg.x, v.y * rn * wreg.y,
                               v.z * rn * wreg.z, v.w * rn * wreg.w);
        float4 rot;
        rot.x = sgn * __shfl_xor_sync(0xffffffffu, n.x, 16);
        rot.y = sgn * __shfl_xor_sync(0xffffffffu, n.y, 16);
        rot.z = sgn * __shfl_xor_sync(0xffffffffu, n.z, 16);
        rot.w = sgn * __shfl_xor_sync(0xffffffffu, n.w, 16);
        float4 c  = *(const float4*)(cosb + bb * HD + lane * 4);
        float4 sn = *(const float4*)(sinb + bb * HD + lane * 4);
        float4 o4 = make_float4(n.x * c.x + rot.x * sn.x,
                                n.y * c.y + rot.y * sn.y,
                                n.z * c.z + rot.z * sn.z,
                                n.w * c.w + rot.w * sn.w);
        if (isq) *(float4*)&g_q[bb][head][lane * 4] = o4;
        else     *(float4*)&g_kn[bb][head - NH][lane * 4] = o4;
    }
    if (t == 0) g_hcnt[head] = 0;   // reset for next graph replay
}

// ---------------------------------------------------------------------------
// 2. Fused flash-decode chunk kernel + tail combine. Grid 512, 256 threads.
// ---------------------------------------------------------------------------
__global__ __launch_bounds__(256) void k_attn(const float* __restrict__ kcache,
                                              const float* __restrict__ vcache,
                                              const float* __restrict__ kpm,
                                              float* __restrict__ outk,
                                              float* __restrict__ outv) {
    int id    = blockIdx.x;
    int chunk = id & (SC - 1);
    int kvh   = (id >> 2) & (NKV - 1);
    int b     = id >> 5;
    int s0    = chunk * SLEN;
    int t     = threadIdx.x;   // 256

    __shared__ float q0s[HD], q1s[HD], kns[HD], vns[HD];
    __shared__ __align__(16) float e0[SLEN], e1[SLEN];
    __shared__ float sr0[8], sr1[8];
    __shared__ int s_last;

    if (t < HD) {
        q0s[t] = g_q[b][2 * kvh][t];
        q1s[t] = g_q[b][2 * kvh + 1][t];
        kns[t] = g_kn[b][kvh][t];
        vns[t] = g_qkv[b][NQ + DKV + kvh * HD + t];
    }
    __syncthreads();

    int posb = g_pos[b];
    size_t rowbase = ((size_t)(b * DKV + kvh * HD) * S + s0) >> 2; // float4 idx

    // ---- Phase 1: K copy + scores. Thread t owns float4 column t (256 cols),
    //      loops all HD=128 rows (R2 k_scores structure: proven 74% DRAM).
    {
        int c   = t;                 // 0..CF4-1
        int gs  = s0 + (c << 2);
        int rel = posb - gs;
        const float4* src = (const float4*)kcache + rowbase + c;
        float4*       dst = (float4*)outk + rowbase + c;

        float a00 = 0, a01 = 0, a02 = 0, a03 = 0;
        float a10 = 0, a11 = 0, a12 = 0, a13 = 0;
#pragma unroll 4
        for (int d = 0; d < HD; d++) {
            float4 v = src[(size_t)d * (S / 4)];
            if ((unsigned)rel < 4u) (&v.x)[rel] = kns[d];
            dst[(size_t)d * (S / 4)] = v;
            float q0 = q0s[d], q1 = q1s[d];
            a00 += q0 * v.x; a01 += q0 * v.y; a02 += q0 * v.z; a03 += q0 * v.w;
            a10 += q1 * v.x; a11 += q1 * v.y; a12 += q1 * v.z; a13 += q1 * v.w;
        }

        float4 m = *(const float4*)(kpm + (size_t)b * S + gs);
        *(float4*)&e0[c << 2] = make_float4(
            a00 * SCALE + m.x, a01 * SCALE + m.y,
            a02 * SCALE + m.z, a03 * SCALE + m.w);
        *(float4*)&e1[c << 2] = make_float4(
            a10 * SCALE + m.x, a11 * SCALE + m.y,
            a12 * SCALE + m.z, a13 * SCALE + m.w);
        __syncthreads();
    }

    // ---- Phase 2: local softmax over the chunk (two heads)
    {
        float m0 = -1e30f, m1 = -1e30f;
        for (int s = t; s < SLEN; s += 256) {
            m0 = fmaxf(m0, e0[s]);
            m1 = fmaxf(m1, e1[s]);
        }
#pragma unroll
        for (int o = 16; o; o >>= 1) {
            m0 = fmaxf(m0, __shfl_xor_sync(0xffffffffu, m0, o));
            m1 = fmaxf(m1, __shfl_xor_sync(0xffffffffu, m1, o));
        }
        if ((t & 31) == 0) { sr0[t >> 5] = m0; sr1[t >> 5] = m1; }
        __syncthreads();
        m0 = sr0[0]; m1 = sr1[0];
#pragma unroll
        for (int w = 1; w < 8; w++) {
            m0 = fmaxf(m0, sr0[w]);
            m1 = fmaxf(m1, sr1[w]);
        }
        __syncthreads();

        float s0a = 0.0f, s1a = 0.0f;
        for (int s = t; s < SLEN; s += 256) {
            float x0 = __expf(e0[s] - m0); e0[s] = x0; s0a += x0;
            float x1 = __expf(e1[s] - m1); e1[s] = x1; s1a += x1;
        }
#pragma unroll
        for (int o = 16; o; o >>= 1) {
            s0a += __shfl_xor_sync(0xffffffffu, s0a, o);
            s1a += __shfl_xor_sync(0xffffffffu, s1a, o);
        }
        if ((t & 31) == 0) { sr0[t >> 5] = s0a; sr1[t >> 5] = s1a; }
        __syncthreads();
        if (t == 0) {
            float t0 = 0, t1 = 0;
#pragma unroll
            for (int w = 0; w < 8; w++) { t0 += sr0[w]; t1 += sr1[w]; }
            g_ms[b][2 * kvh][chunk]     = make_float2(m0, t0);
            g_ms[b][2 * kvh + 1][chunk] = make_float2(m1, t1);
        }
        __syncthreads();
    }

    // ---- Phase 3: V copy + partial weighted sums. Warp w owns d rows w,w+8,..
    //      e0/e1 read as float4 (LDS.128, conflict-free). 8 loads in flight/d.
    {
        int warp = t >> 5, lane = t & 31;
        const float4* src = (const float4*)vcache + rowbase;
        float4*       dst = (float4*)outv + rowbase;

        for (int d = warp; d < HD; d += 8) {
            float p0 = 0.0f, p1 = 0.0f;
            size_t rb = (size_t)d * (S / 4);
#pragma unroll
            for (int it = 0; it < CF4 / 32; it++) {
                int si = it * 32 + lane;
                float4 v = src[rb + si];
                int sl = si << 2;
                int rel = posb - (s0 + sl);
                if ((unsigned)rel < 4u) (&v.x)[rel] = vns[d];
                dst[rb + si] = v;
                float4 w0 = *(const float4*)&e0[sl];
                float4 w1 = *(const float4*)&e1[sl];
                p0 += w0.x * v.x + w0.y * v.y + w0.z * v.z + w0.w * v.w;
                p1 += w1.x * v.x + w1.y * v.y + w1.z * v.z + w1.w * v.w;
            }
#pragma unroll
            for (int o = 16; o; o >>= 1) {
                p0 += __shfl_xor_sync(0xffffffffu, p0, o);
                p1 += __shfl_xor_sync(0xffffffffu, p1, o);
            }
            if (lane == 0) {
                g_pout[b][2 * kvh][chunk][d]     = p0;
                g_pout[b][2 * kvh + 1][chunk][d] = p1;
            }
        }
    }

    // ---- Tail: last chunk block for this (b,kvh) combines all SC chunks.
    __threadfence();
    __syncthreads();
    if (t == 0) s_last = atomicAdd(&g_cnt[b][kvh], 1);
    __syncthreads();
    if (s_last == SC - 1) {
        __threadfence();                 // acquire side: other blocks' writes
        int h = 2 * kvh + (t >> 7);      // threads 0..127 -> head0, 128..255 -> head1
        int d = t & (HD - 1);

        float2 ms[SC];
        float po[SC];
        float M = -1e30f;
#pragma unroll
        for (int c = 0; c < SC; c++) {
            ms[c] = g_ms[b][h][c];
            po[c] = g_pout[b][h][c][d];
            M = fmaxf(M, ms[c].x);
        }
        float tot = 0.0f, acc = 0.0f;
#pragma unroll
        for (int c = 0; c < SC; c++) {
            float w = __expf(ms[c].x - M);
            tot += w * ms[c].y;
            acc += w * po[c];
        }
        g_attnout[b][h * HD + d] = acc / tot;
        if (t == 0) g_cnt[b][kvh] = 0;   // reset for next graph replay
    }
}

// ---------------------------------------------------------------------------
// 3. Output projection: 512 blocks x 256 threads; block handles j-rows
//    (j, j+512). Direct loads; attnout stays L1/L2-resident.
// ---------------------------------------------------------------------------
__global__ __launch_bounds__(256) void k_oproj(const float* __restrict__ Wo,
                                               float* __restrict__ out) {
    int j0 = blockIdx.x;
    int j1 = blockIdx.x + 512;
    const float4* wa = (const float4*)(Wo + (size_t)j0 * NQ);
    const float4* wb = (const float4*)(Wo + (size_t)j1 * NQ);

    float acc0[B], acc1[B];
#pragma unroll
    for (int b = 0; b < B; b++) { acc0[b] = 0.0f; acc1[b] = 0.0f; }

#pragma unroll
    for (int i = 0; i < 2; i++) {
        int r = threadIdx.x + i * 256;     // 512 float4 per row
        float4 w0 = wa[r];
        float4 w1 = wb[r];
#pragma unroll
        for (int b = 0; b < B; b++) {
            float4 a = *(const float4*)&g_attnout[b][r << 2];
            acc0[b] += w0.x * a.x + w0.y * a.y + w0.z * a.z + w0.w * a.w;
            acc1[b] += w1.x * a.x + w1.y * a.y + w1.z * a.z + w1.w * a.w;
        }
    }

    __shared__ float red[8][B];
    int lane = threadIdx.x & 31, warp = threadIdx.x >> 5;

    // reduce + write j0
#pragma unroll
    for (int b = 0; b < B; b++) {
        float v = acc0[b];
#pragma unroll
        for (int o = 16; o; o >>= 1) v += __shfl_xor_sync(0xffffffffu, v, o);
        if (lane == 0) red[warp][b] = v;
    }
    __syncthreads();
    if (threadIdx.x < B) {
        float v = 0.0f;
#pragma unroll
        for (int w = 0; w < 8; w++) v += red[w][threadIdx.x];
        out[threadIdx.x * HID + j0] = v;
    }
    __syncthreads();

    // reduce + write j1
#pragma unroll
    for (int b = 0; b < B; b++) {
        float v = acc1[b];
#pragma unroll
        for (int o = 16; o; o >>= 1) v += __shfl_xor_sync(0xffffffffu, v, o);
        if (lane == 0) red[warp][b] = v;
    }
    __syncthreads();
    if (threadIdx.x < B) {
        float v = 0.0f;
#pragma unroll
        for (int w = 0; w < 8; w++) v += red[w][threadIdx.x];
        out[threadIdx.x * HID + j1] = v;
    }
}

// ---------------------------------------------------------------------------
// Launch
// ---------------------------------------------------------------------------
extern "C" void kernel_launch(void* const* d_in, const int* in_sizes, int n_in,
                              void* d_out, int out_size) {
    (void)in_sizes; (void)n_in; (void)out_size;
    const float* x   = (const float*)d_in[0];
    const float* rc  = (const float*)d_in[1];
    const float* rs  = (const float*)d_in[2];
    const float* kpm = (const float*)d_in[3];
    const float* um  = (const float*)d_in[4];
    const float* kc  = (const float*)d_in[5];
    const float* vc  = (const float*)d_in[6];
    const float* Wq  = (const float*)d_in[7];
    const float* Wk  = (const float*)d_in[8];
    const float* Wv  = (const float*)d_in[9];
    const float* Wo  = (const float*)d_in[10];
    const float* qw  = (const float*)d_in[11];
    const float* kw  = (const float*)d_in[12];

    float* out  = (float*)d_out;
    float* outk = out + (size_t)B * HID;
    float* outv = outk + (size_t)B * DKV * S;

    k_qkv<<<QKV_ROWS / 16, 256>>>(x, Wq, Wk, Wv, rc, rs, qw, kw, um);
    k_attn<<<B * NKV * SC, 256>>>(kc, vc, kpm, outk, outv);
    k_oproj<<<512, 256>>>(Wo, out);
}